// round 1
// baseline (speedup 1.0000x reference)
#include <cuda_runtime.h>
#include <cuda_bf16.h>
#include <math.h>

// ---------------------------------------------------------------------------
// Swin Transformer block: B=32, H=W=56, C=192, NH=6, hd=32, WS=7, SS=3
// T = B*H*W = 100352 tokens. All fp32 (round 0: correctness + decent SIMT perf).
// ---------------------------------------------------------------------------

#define T_TOKENS 100352
#define C_DIM    192
#define HID_DIM  768
#define QKV_DIM  576
#define NHEADS   6
#define HDIM     32
#define WSZ      7
#define NWIN     64      // 8x8 windows
#define NTOK     49      // tokens per window

// Scratch (static device globals; no runtime allocation allowed)
__device__ float g_xw  [(size_t)T_TOKENS * C_DIM];   // LN1 + shifted window gather
__device__ float g_qkv [(size_t)T_TOKENS * QKV_DIM]; // qkv projection
__device__ float g_attn[(size_t)T_TOKENS * C_DIM];   // attention output (window order)
__device__ float g_x1  [(size_t)T_TOKENS * C_DIM];   // residual after attention (spatial)
__device__ float g_xn2 [(size_t)T_TOKENS * C_DIM];   // LN2 output
__device__ float g_hid [(size_t)T_TOKENS * HID_DIM]; // fc1+gelu output

// ---------------------------------------------------------------------------
// LayerNorm (warp per row, 192 channels = 6 per lane).
// gather==1: row t is window-order token; source pixel is the shifted-roll
// location in the spatial input. gather==0: identity row mapping.
// ---------------------------------------------------------------------------
__global__ void ln_kernel(const float* __restrict__ x,
                          const float* __restrict__ gamma,
                          const float* __restrict__ beta,
                          float* __restrict__ out, int gather)
{
    int warp = (blockIdx.x * blockDim.x + threadIdx.x) >> 5;
    int lane = threadIdx.x & 31;
    if (warp >= T_TOKENS) return;

    int src = warp;
    if (gather) {
        int b   = warp / (NWIN * NTOK);
        int rem = warp % (NWIN * NTOK);
        int w   = rem / NTOK;
        int n   = rem % NTOK;
        int gh  = ((w >> 3) * WSZ + n / WSZ + 3) % 56;  // roll(-3) inverse
        int gw  = ((w & 7)  * WSZ + n % WSZ + 3) % 56;
        src = (b * 56 + gh) * 56 + gw;
    }
    const float* row = x + (size_t)src * C_DIM;

    float v[6], s = 0.f, sq = 0.f;
#pragma unroll
    for (int k = 0; k < 6; k++) {
        v[k] = row[lane + 32 * k];
        s  += v[k];
        sq += v[k] * v[k];
    }
#pragma unroll
    for (int o = 16; o; o >>= 1) {
        s  += __shfl_xor_sync(0xffffffffu, s,  o);
        sq += __shfl_xor_sync(0xffffffffu, sq, o);
    }
    float mu  = s * (1.f / C_DIM);
    float var = sq * (1.f / C_DIM) - mu * mu;
    float inv = rsqrtf(var + 1e-5f);

    float* orow = out + (size_t)warp * C_DIM;
#pragma unroll
    for (int k = 0; k < 6; k++) {
        int c = lane + 32 * k;
        orow[c] = (v[k] - mu) * inv * gamma[c] + beta[c];
    }
}

// ---------------------------------------------------------------------------
// Windowed attention: one block per (batch-window, head). 128 threads.
// q,k,v tiles 49x32 in smem (padded), scores 49x49, softmax, P @ V.
// Relative-position bias + shift mask computed inline.
// ---------------------------------------------------------------------------
__global__ void attn_kernel(const float* __restrict__ qkv,
                            const float* __restrict__ rpb,
                            float* __restrict__ out)
{
    const int bw   = blockIdx.x / NHEADS;      // b*64 + window
    const int h    = blockIdx.x % NHEADS;
    const int w    = bw % NWIN;
    const int base = bw * NTOK;
    const int tid  = threadIdx.x;

    __shared__ float qs[NTOK][33];
    __shared__ float ks[NTOK][33];
    __shared__ float vs[NTOK][33];
    __shared__ float S [NTOK][50];

    for (int idx = tid; idx < NTOK * HDIM; idx += 128) {
        int i = idx >> 5, d = idx & 31;
        const float* r = qkv + (size_t)(base + i) * QKV_DIM + h * HDIM + d;
        qs[i][d] = r[0];
        ks[i][d] = r[C_DIM];
        vs[i][d] = r[2 * C_DIM];
    }
    __syncthreads();

    const int wh = w >> 3, ww = w & 7;
    for (int idx = tid; idx < NTOK * NTOK; idx += 128) {
        int i = idx / NTOK, j = idx % NTOK;
        float dot = 0.f;
#pragma unroll
        for (int d = 0; d < HDIM; d++) dot += qs[i][d] * ks[j][d];
        int ri = i / WSZ, ci = i % WSZ, rj = j / WSZ, cj = j % WSZ;
        float bias = rpb[((ri - rj + 6) * 13 + (ci - cj + 6)) * NHEADS + h];
        // shift mask: region ids on the *shifted* image grid
        int ghi = wh * WSZ + ri, gwi = ww * WSZ + ci;
        int ghj = wh * WSZ + rj, gwj = ww * WSZ + cj;
        int regI = (ghi < 49 ? 0 : (ghi < 53 ? 1 : 2)) * 3 + (gwi < 49 ? 0 : (gwi < 53 ? 1 : 2));
        int regJ = (ghj < 49 ? 0 : (ghj < 53 ? 1 : 2)) * 3 + (gwj < 49 ? 0 : (gwj < 53 ? 1 : 2));
        float m = (regI != regJ) ? -100.f : 0.f;
        S[i][j] = dot * 0.17677669529663687f + bias + m;  // scale = 32^-0.5
    }
    __syncthreads();

    if (tid < NTOK) {
        int i = tid;
        float mx = -1e30f;
#pragma unroll 7
        for (int j = 0; j < NTOK; j++) mx = fmaxf(mx, S[i][j]);
        float sum = 0.f;
#pragma unroll 7
        for (int j = 0; j < NTOK; j++) { float e = expf(S[i][j] - mx); S[i][j] = e; sum += e; }
        float r = 1.f / sum;
#pragma unroll 7
        for (int j = 0; j < NTOK; j++) S[i][j] *= r;
    }
    __syncthreads();

    for (int idx = tid; idx < NTOK * HDIM; idx += 128) {
        int i = idx >> 5, d = idx & 31;
        float acc = 0.f;
#pragma unroll 7
        for (int j = 0; j < NTOK; j++) acc += S[i][j] * vs[j][d];
        out[(size_t)(base + i) * C_DIM + h * HDIM + d] = acc;
    }
}

// ---------------------------------------------------------------------------
// SGEMM: C(MxN) = A(MxK, row-major) @ B(KxN, row-major) + epilogue.
// BM=128, BN=128, BK=8, 256 threads, 8x8 per-thread tile.
// M is always a multiple of 128 (100352 = 784*128); K multiple of 8; N
// multiple of 4 (576/192/768) -> only the N edge needs guarding.
// MODE 0: + bias                               (qkv)
// MODE 1: + bias + resid[spatial], scatter window->spatial+roll   (proj)
// MODE 2: gelu(acc + bias)                     (fc1)
// MODE 3: + bias + resid (same row layout)     (fc2, writes d_out)
// ---------------------------------------------------------------------------
template <int MODE>
__global__ void sgemm_ep(const float* __restrict__ A, const float* __restrict__ B,
                         const float* __restrict__ bias, const float* __restrict__ resid,
                         float* __restrict__ C, int M, int N, int K)
{
    __shared__ float As[8][128];
    __shared__ float Bs[8][128];

    const int bm = blockIdx.y, bn = blockIdx.x;
    const int tid = threadIdx.x;

    const int arow  = tid >> 1;             // 0..127
    const int ak    = (tid & 1) * 4;        // 0 or 4
    const int bk    = tid >> 5;             // 0..7
    const int bncol = (tid & 31) * 4;       // 0..124

    const int tx = tid & 15;                // col group
    const int ty = tid >> 4;                // row group

    float acc[8][8];
#pragma unroll
    for (int i = 0; i < 8; i++)
#pragma unroll
        for (int j = 0; j < 8; j++) acc[i][j] = 0.f;

    const int gArow = bm * 128 + arow;
    const int gBn   = bn * 128 + bncol;
    const bool bok  = (gBn < N);

    for (int k0 = 0; k0 < K; k0 += 8) {
        float4 a4 = *reinterpret_cast<const float4*>(&A[(size_t)gArow * K + k0 + ak]);
        As[ak + 0][arow] = a4.x; As[ak + 1][arow] = a4.y;
        As[ak + 2][arow] = a4.z; As[ak + 3][arow] = a4.w;

        float4 b4 = bok ? *reinterpret_cast<const float4*>(&B[(size_t)(k0 + bk) * N + gBn])
                        : make_float4(0.f, 0.f, 0.f, 0.f);
        *reinterpret_cast<float4*>(&Bs[bk][bncol]) = b4;
        __syncthreads();

#pragma unroll
        for (int kk = 0; kk < 8; kk++) {
            float ra[8], rb[8];
#pragma unroll
            for (int i = 0; i < 8; i++) ra[i] = As[kk][ty * 8 + i];
#pragma unroll
            for (int j = 0; j < 8; j++) rb[j] = Bs[kk][tx * 8 + j];
#pragma unroll
            for (int i = 0; i < 8; i++)
#pragma unroll
                for (int j = 0; j < 8; j++) acc[i][j] += ra[i] * rb[j];
        }
        __syncthreads();
    }

#pragma unroll
    for (int i = 0; i < 8; i++) {
        int row = bm * 128 + ty * 8 + i;
        int prow = row;
        if (MODE == 1) {
            // window-order row -> spatial pixel (window reverse + roll(+3))
            int b   = row / (NWIN * NTOK);
            int rem = row % (NWIN * NTOK);
            int w   = rem / NTOK;
            int n   = rem % NTOK;
            int gh  = ((w >> 3) * WSZ + n / WSZ + 3) % 56;
            int gw  = ((w & 7)  * WSZ + n % WSZ + 3) % 56;
            prow = (b * 56 + gh) * 56 + gw;
        }
#pragma unroll
        for (int j = 0; j < 8; j++) {
            int col = bn * 128 + tx * 8 + j;
            if (col < N) {
                float v = acc[i][j] + bias[col];
                if (MODE == 1) {
                    v += resid[(size_t)prow * N + col];
                    C[(size_t)prow * N + col] = v;
                } else if (MODE == 2) {
                    v = 0.5f * v * (1.f + erff(v * 0.70710678118654752f));
                    C[(size_t)row * N + col] = v;
                } else if (MODE == 3) {
                    v += resid[(size_t)row * N + col];
                    C[(size_t)row * N + col] = v;
                } else {
                    C[(size_t)row * N + col] = v;
                }
            }
        }
    }
}

// ---------------------------------------------------------------------------
// Launch
// ---------------------------------------------------------------------------
extern "C" void kernel_launch(void* const* d_in, const int* in_sizes, int n_in,
                              void* d_out, int out_size)
{
    const float* x      = (const float*)d_in[0];
    const float* n1g    = (const float*)d_in[1];
    const float* n1b    = (const float*)d_in[2];
    const float* qkv_w  = (const float*)d_in[3];
    const float* qkv_b  = (const float*)d_in[4];
    const float* rpb    = (const float*)d_in[5];
    const float* proj_w = (const float*)d_in[6];
    const float* proj_b = (const float*)d_in[7];
    const float* n2g    = (const float*)d_in[8];
    const float* n2b    = (const float*)d_in[9];
    const float* fc1_w  = (const float*)d_in[10];
    const float* fc1_b  = (const float*)d_in[11];
    const float* fc2_w  = (const float*)d_in[12];
    const float* fc2_b  = (const float*)d_in[13];
    float* out = (float*)d_out;

    float *xw, *qkvbuf, *attn, *x1, *xn2, *hid;
    cudaGetSymbolAddress((void**)&xw,     g_xw);
    cudaGetSymbolAddress((void**)&qkvbuf, g_qkv);
    cudaGetSymbolAddress((void**)&attn,   g_attn);
    cudaGetSymbolAddress((void**)&x1,     g_x1);
    cudaGetSymbolAddress((void**)&xn2,    g_xn2);
    cudaGetSymbolAddress((void**)&hid,    g_hid);

    const int lnBlocks = (T_TOKENS + 7) / 8;    // 8 warps per 256-thread block

    // 1. LN1 + shift + window partition
    ln_kernel<<<lnBlocks, 256>>>(x, n1g, n1b, xw, 1);

    // 2. QKV GEMM: [T,192] @ [192,576]
    sgemm_ep<0><<<dim3((QKV_DIM + 127) / 128, T_TOKENS / 128), 256>>>(
        xw, qkv_w, qkv_b, nullptr, qkvbuf, T_TOKENS, QKV_DIM, C_DIM);

    // 3. Attention per (window, head)
    attn_kernel<<<(T_TOKENS / NTOK) * NHEADS, 128>>>(qkvbuf, rpb, attn);

    // 4. Proj GEMM + window reverse + roll + residual
    sgemm_ep<1><<<dim3((C_DIM + 127) / 128, T_TOKENS / 128), 256>>>(
        attn, proj_w, proj_b, x, x1, T_TOKENS, C_DIM, C_DIM);

    // 5. LN2
    ln_kernel<<<lnBlocks, 256>>>(x1, n2g, n2b, xn2, 0);

    // 6. FC1 GEMM + exact GELU
    sgemm_ep<2><<<dim3((HID_DIM + 127) / 128, T_TOKENS / 128), 256>>>(
        xn2, fc1_w, fc1_b, nullptr, hid, T_TOKENS, HID_DIM, C_DIM);

    // 7. FC2 GEMM + residual -> output
    sgemm_ep<3><<<dim3((C_DIM + 127) / 128, T_TOKENS / 128), 256>>>(
        hid, fc2_w, fc2_b, x1, out, T_TOKENS, C_DIM, HID_DIM);
}

// round 4
// speedup vs baseline: 3.2649x; 3.2649x over previous
#include <cuda_runtime.h>
#include <cuda_fp16.h>
#include <math.h>
#include <stdint.h>

// ---------------------------------------------------------------------------
// Swin block: B=32, H=W=56, C=192, NH=6, hd=32, WS=7, SS=3. T=100352 tokens.
// Round 4: resubmit of round-3 HMMA design (round-3 bench died to container
// infra, not the kernel). GEMMs via mma.sync.m16n8k16 fp16->fp32.
// ---------------------------------------------------------------------------

#define T_TOKENS 100352
#define C_DIM    192
#define HID_DIM  768
#define QKV_DIM  576
#define NHEADS   6
#define HDIM     32
#define WSZ      7
#define NWIN     64
#define NTOK     49
#define MTILES   (T_TOKENS / 128)   // 784

// Scratch (static device globals; no runtime allocation allowed)
__device__ __half g_xw  [(size_t)T_TOKENS * C_DIM];
__device__ __half g_qkv [(size_t)T_TOKENS * QKV_DIM];
__device__ __half g_attn[(size_t)T_TOKENS * C_DIM];
__device__ float  g_x1  [(size_t)T_TOKENS * C_DIM];
__device__ __half g_xn2 [(size_t)T_TOKENS * C_DIM];
__device__ __half g_hid [(size_t)T_TOKENS * HID_DIM];
// fp16 transposed weights: w_t[n][k] = w[k][n]
__device__ __half g_wqkv [(size_t)QKV_DIM * C_DIM];
__device__ __half g_wproj[(size_t)C_DIM * C_DIM];
__device__ __half g_wfc1 [(size_t)HID_DIM * C_DIM];
__device__ __half g_wfc2 [(size_t)C_DIM * HID_DIM];

__device__ __forceinline__ uint32_t smem_u32(const void* p) {
    return (uint32_t)__cvta_generic_to_shared(p);
}

__device__ __forceinline__ void cp_async16(uint32_t dst, const void* src) {
    asm volatile("cp.async.cg.shared.global [%0], [%1], 16;" :: "r"(dst), "l"(src));
}
__device__ __forceinline__ void cp_commit() {
    asm volatile("cp.async.commit_group;");
}
__device__ __forceinline__ void cp_wait1() {
    asm volatile("cp.async.wait_group 1;");
}
__device__ __forceinline__ void cp_wait0() {
    asm volatile("cp.async.wait_group 0;");
}

__device__ __forceinline__ void mma16816(float* c, const uint32_t* a,
                                         uint32_t b0, uint32_t b1) {
    asm volatile(
        "mma.sync.aligned.m16n8k16.row.col.f32.f16.f16.f32 "
        "{%0,%1,%2,%3}, {%4,%5,%6,%7}, {%8,%9}, {%0,%1,%2,%3};"
        : "+f"(c[0]), "+f"(c[1]), "+f"(c[2]), "+f"(c[3])
        : "r"(a[0]), "r"(a[1]), "r"(a[2]), "r"(a[3]), "r"(b0), "r"(b1));
}

// ---------------------------------------------------------------------------
// Weight prep: transpose + fp16 convert
// ---------------------------------------------------------------------------
#define W_QKV_E (QKV_DIM * C_DIM)
#define W_PRJ_E (C_DIM * C_DIM)
#define W_FC1_E (HID_DIM * C_DIM)
#define W_FC2_E (C_DIM * HID_DIM)
#define W_TOTAL (W_QKV_E + W_PRJ_E + W_FC1_E + W_FC2_E)

__global__ void prep_weights(const float* __restrict__ qkv_w,
                             const float* __restrict__ proj_w,
                             const float* __restrict__ fc1_w,
                             const float* __restrict__ fc2_w)
{
    int i = blockIdx.x * blockDim.x + threadIdx.x;
    if (i >= W_TOTAL) return;
    if (i < W_QKV_E) {
        int n = i / C_DIM, k = i % C_DIM;
        g_wqkv[i] = __float2half(qkv_w[k * QKV_DIM + n]);
    } else if (i < W_QKV_E + W_PRJ_E) {
        int j = i - W_QKV_E;
        int n = j / C_DIM, k = j % C_DIM;
        g_wproj[j] = __float2half(proj_w[k * C_DIM + n]);
    } else if (i < W_QKV_E + W_PRJ_E + W_FC1_E) {
        int j = i - W_QKV_E - W_PRJ_E;
        int n = j / C_DIM, k = j % C_DIM;
        g_wfc1[j] = __float2half(fc1_w[k * HID_DIM + n]);
    } else {
        int j = i - W_QKV_E - W_PRJ_E - W_FC1_E;
        int n = j / HID_DIM, k = j % HID_DIM;
        g_wfc2[j] = __float2half(fc2_w[k * C_DIM + n]);
    }
}

// ---------------------------------------------------------------------------
// LayerNorm (warp per row), optional shifted-window gather, fp16 out.
// ---------------------------------------------------------------------------
__global__ void ln_kernel(const float* __restrict__ x,
                          const float* __restrict__ gamma,
                          const float* __restrict__ beta,
                          __half* __restrict__ out, int gather)
{
    int warp = (blockIdx.x * blockDim.x + threadIdx.x) >> 5;
    int lane = threadIdx.x & 31;
    if (warp >= T_TOKENS) return;

    int src = warp;
    if (gather) {
        int b   = warp / (NWIN * NTOK);
        int rem = warp % (NWIN * NTOK);
        int w   = rem / NTOK;
        int n   = rem % NTOK;
        int gh  = ((w >> 3) * WSZ + n / WSZ + 3) % 56;
        int gw  = ((w & 7)  * WSZ + n % WSZ + 3) % 56;
        src = (b * 56 + gh) * 56 + gw;
    }
    const float* row = x + (size_t)src * C_DIM;

    float v[6], s = 0.f, sq = 0.f;
#pragma unroll
    for (int k = 0; k < 6; k++) {
        v[k] = row[lane + 32 * k];
        s += v[k]; sq += v[k] * v[k];
    }
#pragma unroll
    for (int o = 16; o; o >>= 1) {
        s  += __shfl_xor_sync(0xffffffffu, s,  o);
        sq += __shfl_xor_sync(0xffffffffu, sq, o);
    }
    float mu  = s * (1.f / C_DIM);
    float var = sq * (1.f / C_DIM) - mu * mu;
    float inv = rsqrtf(var + 1e-5f);

    __half* orow = out + (size_t)warp * C_DIM;
#pragma unroll
    for (int k = 0; k < 6; k++) {
        int c = lane + 32 * k;
        orow[c] = __float2half((v[k] - mu) * inv * gamma[c] + beta[c]);
    }
}

// ---------------------------------------------------------------------------
// Windowed attention (fp16 qkv in, fp16 out), one block per (window, head).
// ---------------------------------------------------------------------------
__global__ void attn_kernel(const __half* __restrict__ qkv,
                            const float* __restrict__ rpb,
                            __half* __restrict__ out)
{
    const int bw   = blockIdx.x / NHEADS;
    const int h    = blockIdx.x % NHEADS;
    const int w    = bw % NWIN;
    const int base = bw * NTOK;
    const int tid  = threadIdx.x;

    __shared__ float qs[NTOK][33];
    __shared__ float ks[NTOK][33];
    __shared__ float vs[NTOK][33];
    __shared__ float S [NTOK][50];

    for (int idx = tid; idx < NTOK * HDIM; idx += 128) {
        int i = idx >> 5, d = idx & 31;
        const __half* r = qkv + (size_t)(base + i) * QKV_DIM + h * HDIM + d;
        qs[i][d] = __half2float(r[0]);
        ks[i][d] = __half2float(r[C_DIM]);
        vs[i][d] = __half2float(r[2 * C_DIM]);
    }
    __syncthreads();

    const int wh = w >> 3, ww = w & 7;
    for (int idx = tid; idx < NTOK * NTOK; idx += 128) {
        int i = idx / NTOK, j = idx % NTOK;
        float dot = 0.f;
#pragma unroll
        for (int d = 0; d < HDIM; d++) dot += qs[i][d] * ks[j][d];
        int ri = i / WSZ, ci = i % WSZ, rj = j / WSZ, cj = j % WSZ;
        float bias = rpb[((ri - rj + 6) * 13 + (ci - cj + 6)) * NHEADS + h];
        int ghi = wh * WSZ + ri, gwi = ww * WSZ + ci;
        int ghj = wh * WSZ + rj, gwj = ww * WSZ + cj;
        int regI = (ghi < 49 ? 0 : (ghi < 53 ? 1 : 2)) * 3 + (gwi < 49 ? 0 : (gwi < 53 ? 1 : 2));
        int regJ = (ghj < 49 ? 0 : (ghj < 53 ? 1 : 2)) * 3 + (gwj < 49 ? 0 : (gwj < 53 ? 1 : 2));
        float m = (regI != regJ) ? -100.f : 0.f;
        S[i][j] = dot * 0.17677669529663687f + bias + m;
    }
    __syncthreads();

    if (tid < NTOK) {
        int i = tid;
        float mx = -1e30f;
#pragma unroll 7
        for (int j = 0; j < NTOK; j++) mx = fmaxf(mx, S[i][j]);
        float sum = 0.f;
#pragma unroll 7
        for (int j = 0; j < NTOK; j++) { float e = expf(S[i][j] - mx); S[i][j] = e; sum += e; }
        float r = 1.f / sum;
#pragma unroll 7
        for (int j = 0; j < NTOK; j++) S[i][j] *= r;
    }
    __syncthreads();

    for (int idx = tid; idx < NTOK * HDIM; idx += 128) {
        int i = idx >> 5, d = idx & 31;
        float acc = 0.f;
#pragma unroll 7
        for (int j = 0; j < NTOK; j++) acc += S[i][j] * vs[j][d];
        out[(size_t)(base + i) * C_DIM + h * HDIM + d] = __float2half(acc);
    }
}

// ---------------------------------------------------------------------------
// HMMA GEMM: C[128 x 96-tile] = A[M,K] @ Bw^T, Bw is [N][K] fp16 (row.col).
// BM=128, BN=96, BK=32, 256 threads (4x2 warps, warp tile 32x48).
// cp.async double-buffered. N is a multiple of 96 -> no guards anywhere.
// MODE 0: +bias -> fp16                                    (qkv)
// MODE 1: +bias+resid[spatial], window-reverse scatter -> fp32 (proj)
// MODE 2: gelu(+bias) -> fp16                              (fc1)
// MODE 3: +bias+resid -> fp32                              (fc2 -> d_out)
// ---------------------------------------------------------------------------
#define BK      32
#define LDS_A   40     // halves per row (32 + 8 pad): conflict-free frag loads
#define LDS_B   40

template <int MODE>
__global__ void __launch_bounds__(256)
hmma_gemm(const __half* __restrict__ A, const __half* __restrict__ Bw,
          const float* __restrict__ bias, const float* __restrict__ resid,
          void* __restrict__ Cout, int N, int K)
{
    __shared__ __half As[2][128 * LDS_A];
    __shared__ __half Bs[2][96 * LDS_B];

    const int tid    = threadIdx.x;
    const int warp   = tid >> 5;
    const int lane   = tid & 31;
    const int warp_m = warp & 3;   // 4 row-warps of 32 rows
    const int warp_n = warp >> 2;  // 2 col-warps of 48 cols
    const int bm = blockIdx.y, bn = blockIdx.x;

    const int g = lane >> 2;       // group id 0..7
    const int t = lane & 3;        // thread in group

    float acc[2][6][4];
#pragma unroll
    for (int mt = 0; mt < 2; mt++)
#pragma unroll
        for (int nt = 0; nt < 6; nt++)
#pragma unroll
            for (int e = 0; e < 4; e++) acc[mt][nt][e] = 0.f;

    const int NC = K >> 5;   // BK=32 chunks

    auto load_chunk = [&](int c) {
        const int p  = c & 1;
        const int k0 = c << 5;
        // A: 128 rows x 32 halves = 512 x 16B
#pragma unroll
        for (int i = tid; i < 512; i += 256) {
            int r = i >> 2, s = i & 3;
            cp_async16(smem_u32(&As[p][r * LDS_A + s * 8]),
                       A + (size_t)(bm * 128 + r) * K + k0 + s * 8);
        }
        // B: 96 rows x 32 halves = 384 x 16B
        for (int i = tid; i < 384; i += 256) {
            int r = i >> 2, s = i & 3;
            cp_async16(smem_u32(&Bs[p][r * LDS_B + s * 8]),
                       Bw + (size_t)(bn * 96 + r) * K + k0 + s * 8);
        }
        cp_commit();
    };

    load_chunk(0);

    for (int c = 0; c < NC; c++) {
        if (c + 1 < NC) { load_chunk(c + 1); cp_wait1(); }
        else            { cp_wait0(); }
        __syncthreads();

        const int p = c & 1;
        const __half* a_s = As[p];
        const __half* b_s = Bs[p];

#pragma unroll
        for (int ksub = 0; ksub < 2; ksub++) {
            const int kb = ksub * 16 + t * 2;
            uint32_t afr[2][4];
#pragma unroll
            for (int mt = 0; mt < 2; mt++) {
                int r0 = warp_m * 32 + mt * 16 + g;
                afr[mt][0] = *(const uint32_t*)&a_s[r0 * LDS_A + kb];
                afr[mt][1] = *(const uint32_t*)&a_s[(r0 + 8) * LDS_A + kb];
                afr[mt][2] = *(const uint32_t*)&a_s[r0 * LDS_A + kb + 8];
                afr[mt][3] = *(const uint32_t*)&a_s[(r0 + 8) * LDS_A + kb + 8];
            }
#pragma unroll
            for (int nt = 0; nt < 6; nt++) {
                int n0 = warp_n * 48 + nt * 8 + g;
                uint32_t b0 = *(const uint32_t*)&b_s[n0 * LDS_B + kb];
                uint32_t b1 = *(const uint32_t*)&b_s[n0 * LDS_B + kb + 8];
                mma16816(acc[0][nt], afr[0], b0, b1);
                mma16816(acc[1][nt], afr[1], b0, b1);
            }
        }
        __syncthreads();
    }

    // --- epilogue ----------------------------------------------------------
#pragma unroll
    for (int mt = 0; mt < 2; mt++) {
        int row = bm * 128 + warp_m * 32 + mt * 16 + g;  // and row+8
        int orow0 = row, orow1 = row + 8;
        if (MODE == 1) {
#pragma unroll
            for (int rr = 0; rr < 2; rr++) {
                int r   = row + rr * 8;
                int b   = r / (NWIN * NTOK);
                int rem = r % (NWIN * NTOK);
                int w   = rem / NTOK;
                int n   = rem % NTOK;
                int gh  = ((w >> 3) * WSZ + n / WSZ + 3) % 56;
                int gw  = ((w & 7)  * WSZ + n % WSZ + 3) % 56;
                int pr  = (b * 56 + gh) * 56 + gw;
                if (rr) orow1 = pr; else orow0 = pr;
            }
        }
#pragma unroll
        for (int nt = 0; nt < 6; nt++) {
            int col = bn * 96 + warp_n * 48 + nt * 8 + t * 2;
            float b0 = bias[col], b1 = bias[col + 1];
            float v0 = acc[mt][nt][0] + b0;
            float v1 = acc[mt][nt][1] + b1;
            float v2 = acc[mt][nt][2] + b0;
            float v3 = acc[mt][nt][3] + b1;
            if (MODE == 0) {
                __half* O = (__half*)Cout;
                *(__half2*)(O + (size_t)row * N + col)       = __floats2half2_rn(v0, v1);
                *(__half2*)(O + (size_t)(row + 8) * N + col) = __floats2half2_rn(v2, v3);
            } else if (MODE == 2) {
                v0 = 0.5f * v0 * (1.f + erff(v0 * 0.70710678118654752f));
                v1 = 0.5f * v1 * (1.f + erff(v1 * 0.70710678118654752f));
                v2 = 0.5f * v2 * (1.f + erff(v2 * 0.70710678118654752f));
                v3 = 0.5f * v3 * (1.f + erff(v3 * 0.70710678118654752f));
                __half* O = (__half*)Cout;
                *(__half2*)(O + (size_t)row * N + col)       = __floats2half2_rn(v0, v1);
                *(__half2*)(O + (size_t)(row + 8) * N + col) = __floats2half2_rn(v2, v3);
            } else {
                float* O = (float*)Cout;
                const float2 r0 = *(const float2*)(resid + (size_t)orow0 * N + col);
                const float2 r1 = *(const float2*)(resid + (size_t)orow1 * N + col);
                float2 o0 = make_float2(v0 + r0.x, v1 + r0.y);
                float2 o1 = make_float2(v2 + r1.x, v3 + r1.y);
                *(float2*)(O + (size_t)orow0 * N + col) = o0;
                *(float2*)(O + (size_t)orow1 * N + col) = o1;
            }
        }
    }
}

// ---------------------------------------------------------------------------
// Launch
// ---------------------------------------------------------------------------
extern "C" void kernel_launch(void* const* d_in, const int* in_sizes, int n_in,
                              void* d_out, int out_size)
{
    const float* x      = (const float*)d_in[0];
    const float* n1g    = (const float*)d_in[1];
    const float* n1b    = (const float*)d_in[2];
    const float* qkv_w  = (const float*)d_in[3];
    const float* qkv_b  = (const float*)d_in[4];
    const float* rpb    = (const float*)d_in[5];
    const float* proj_w = (const float*)d_in[6];
    const float* proj_b = (const float*)d_in[7];
    const float* n2g    = (const float*)d_in[8];
    const float* n2b    = (const float*)d_in[9];
    const float* fc1_w  = (const float*)d_in[10];
    const float* fc1_b  = (const float*)d_in[11];
    const float* fc2_w  = (const float*)d_in[12];
    const float* fc2_b  = (const float*)d_in[13];
    float* out = (float*)d_out;

    __half *xw, *qkvb, *attn, *xn2, *hid, *wqkv, *wproj, *wfc1, *wfc2;
    float  *x1;
    cudaGetSymbolAddress((void**)&xw,    g_xw);
    cudaGetSymbolAddress((void**)&qkvb,  g_qkv);
    cudaGetSymbolAddress((void**)&attn,  g_attn);
    cudaGetSymbolAddress((void**)&x1,    g_x1);
    cudaGetSymbolAddress((void**)&xn2,   g_xn2);
    cudaGetSymbolAddress((void**)&hid,   g_hid);
    cudaGetSymbolAddress((void**)&wqkv,  g_wqkv);
    cudaGetSymbolAddress((void**)&wproj, g_wproj);
    cudaGetSymbolAddress((void**)&wfc1,  g_wfc1);
    cudaGetSymbolAddress((void**)&wfc2,  g_wfc2);

    const int lnBlocks = (T_TOKENS + 7) / 8;

    // 0. weights -> fp16 transposed
    prep_weights<<<(W_TOTAL + 255) / 256, 256>>>(qkv_w, proj_w, fc1_w, fc2_w);

    // 1. LN1 + shift + window partition (fp16 out)
    ln_kernel<<<lnBlocks, 256>>>(x, n1g, n1b, xw, 1);

    // 2. QKV: [T,192] @ [192,576]
    hmma_gemm<0><<<dim3(QKV_DIM / 96, MTILES), 256>>>(
        xw, wqkv, qkv_b, nullptr, qkvb, QKV_DIM, C_DIM);

    // 3. Attention
    attn_kernel<<<(T_TOKENS / NTOK) * NHEADS, 128>>>(qkvb, rpb, attn);

    // 4. Proj + window reverse + roll + residual (fp32 x1)
    hmma_gemm<1><<<dim3(C_DIM / 96, MTILES), 256>>>(
        attn, wproj, proj_b, x, x1, C_DIM, C_DIM);

    // 5. LN2 (fp16 out)
    ln_kernel<<<lnBlocks, 256>>>(x1, n2g, n2b, xn2, 0);

    // 6. FC1 + exact GELU (fp16 out)
    hmma_gemm<2><<<dim3(HID_DIM / 96, MTILES), 256>>>(
        xn2, wfc1, fc1_b, nullptr, hid, HID_DIM, C_DIM);

    // 7. FC2 + residual -> output (fp32)
    hmma_gemm<3><<<dim3(C_DIM / 96, MTILES), 256>>>(
        hid, wfc2, fc2_b, x1, out, C_DIM, HID_DIM);
}

// round 5
// speedup vs baseline: 5.3609x; 1.6420x over previous
#include <cuda_runtime.h>
#include <cuda_fp16.h>
#include <math.h>
#include <stdint.h>

// ---------------------------------------------------------------------------
// Swin block: B=32, H=W=56, C=192, NH=6, hd=32, WS=7, SS=3. T=100352 tokens.
// Round 5: attention moved to HMMA (m16n8k16) with in-register softmax.
// GEMMs unchanged from round 4 (HMMA fp16->fp32).
// ---------------------------------------------------------------------------

#define T_TOKENS 100352
#define C_DIM    192
#define HID_DIM  768
#define QKV_DIM  576
#define NHEADS   6
#define HDIM     32
#define WSZ      7
#define NWIN     64
#define NTOK     49
#define MTILES   (T_TOKENS / 128)   // 784

__device__ __half g_xw  [(size_t)T_TOKENS * C_DIM];
__device__ __half g_qkv [(size_t)T_TOKENS * QKV_DIM];
__device__ __half g_attn[(size_t)T_TOKENS * C_DIM];
__device__ float  g_x1  [(size_t)T_TOKENS * C_DIM];
__device__ __half g_xn2 [(size_t)T_TOKENS * C_DIM];
__device__ __half g_hid [(size_t)T_TOKENS * HID_DIM];
__device__ __half g_wqkv [(size_t)QKV_DIM * C_DIM];
__device__ __half g_wproj[(size_t)C_DIM * C_DIM];
__device__ __half g_wfc1 [(size_t)HID_DIM * C_DIM];
__device__ __half g_wfc2 [(size_t)C_DIM * HID_DIM];

__device__ __forceinline__ uint32_t smem_u32(const void* p) {
    return (uint32_t)__cvta_generic_to_shared(p);
}
__device__ __forceinline__ void cp_async16(uint32_t dst, const void* src) {
    asm volatile("cp.async.cg.shared.global [%0], [%1], 16;" :: "r"(dst), "l"(src));
}
__device__ __forceinline__ void cp_commit() { asm volatile("cp.async.commit_group;"); }
__device__ __forceinline__ void cp_wait1()  { asm volatile("cp.async.wait_group 1;"); }
__device__ __forceinline__ void cp_wait0()  { asm volatile("cp.async.wait_group 0;"); }

__device__ __forceinline__ void mma16816(float* c, const uint32_t* a,
                                         uint32_t b0, uint32_t b1) {
    asm volatile(
        "mma.sync.aligned.m16n8k16.row.col.f32.f16.f16.f32 "
        "{%0,%1,%2,%3}, {%4,%5,%6,%7}, {%8,%9}, {%0,%1,%2,%3};"
        : "+f"(c[0]), "+f"(c[1]), "+f"(c[2]), "+f"(c[3])
        : "r"(a[0]), "r"(a[1]), "r"(a[2]), "r"(a[3]), "r"(b0), "r"(b1));
}

// ---------------------------------------------------------------------------
// Weight prep
// ---------------------------------------------------------------------------
#define W_QKV_E (QKV_DIM * C_DIM)
#define W_PRJ_E (C_DIM * C_DIM)
#define W_FC1_E (HID_DIM * C_DIM)
#define W_FC2_E (C_DIM * HID_DIM)
#define W_TOTAL (W_QKV_E + W_PRJ_E + W_FC1_E + W_FC2_E)

__global__ void prep_weights(const float* __restrict__ qkv_w,
                             const float* __restrict__ proj_w,
                             const float* __restrict__ fc1_w,
                             const float* __restrict__ fc2_w)
{
    int i = blockIdx.x * blockDim.x + threadIdx.x;
    if (i >= W_TOTAL) return;
    if (i < W_QKV_E) {
        int n = i / C_DIM, k = i % C_DIM;
        g_wqkv[i] = __float2half(qkv_w[k * QKV_DIM + n]);
    } else if (i < W_QKV_E + W_PRJ_E) {
        int j = i - W_QKV_E;
        int n = j / C_DIM, k = j % C_DIM;
        g_wproj[j] = __float2half(proj_w[k * C_DIM + n]);
    } else if (i < W_QKV_E + W_PRJ_E + W_FC1_E) {
        int j = i - W_QKV_E - W_PRJ_E;
        int n = j / C_DIM, k = j % C_DIM;
        g_wfc1[j] = __float2half(fc1_w[k * HID_DIM + n]);
    } else {
        int j = i - W_QKV_E - W_PRJ_E - W_FC1_E;
        int n = j / HID_DIM, k = j % HID_DIM;
        g_wfc2[j] = __float2half(fc2_w[k * C_DIM + n]);
    }
}

// ---------------------------------------------------------------------------
// LayerNorm (warp per row), optional shifted-window gather, fp16 out.
// ---------------------------------------------------------------------------
__global__ void ln_kernel(const float* __restrict__ x,
                          const float* __restrict__ gamma,
                          const float* __restrict__ beta,
                          __half* __restrict__ out, int gather)
{
    int warp = (blockIdx.x * blockDim.x + threadIdx.x) >> 5;
    int lane = threadIdx.x & 31;
    if (warp >= T_TOKENS) return;

    int src = warp;
    if (gather) {
        int b   = warp / (NWIN * NTOK);
        int rem = warp % (NWIN * NTOK);
        int w   = rem / NTOK;
        int n   = rem % NTOK;
        int gh  = ((w >> 3) * WSZ + n / WSZ + 3) % 56;
        int gw  = ((w & 7)  * WSZ + n % WSZ + 3) % 56;
        src = (b * 56 + gh) * 56 + gw;
    }
    const float* row = x + (size_t)src * C_DIM;

    float v[6], s = 0.f, sq = 0.f;
#pragma unroll
    for (int k = 0; k < 6; k++) {
        v[k] = row[lane + 32 * k];
        s += v[k]; sq += v[k] * v[k];
    }
#pragma unroll
    for (int o = 16; o; o >>= 1) {
        s  += __shfl_xor_sync(0xffffffffu, s,  o);
        sq += __shfl_xor_sync(0xffffffffu, sq, o);
    }
    float mu  = s * (1.f / C_DIM);
    float var = sq * (1.f / C_DIM) - mu * mu;
    float inv = rsqrtf(var + 1e-5f);

    __half* orow = out + (size_t)warp * C_DIM;
#pragma unroll
    for (int k = 0; k < 6; k++) {
        int c = lane + 32 * k;
        orow[c] = __float2half((v[k] - mu) * inv * gamma[c] + beta[c]);
    }
}

// ---------------------------------------------------------------------------
// HMMA windowed attention. One block = (window, head), 128 threads (4 warps).
// N padded 49->64. S = Q@K^T (fp32 accum) with bias/mask in regs, softmax in
// register fragments (quad shuffles), P fp16 -> smem, O = P@V via HMMA.
// ---------------------------------------------------------------------------
#define QK_STR  40    // q/k smem row stride (32 + 8 pad) halves
#define PV_STR  72    // p / vT smem row stride (64 + 8 pad) halves

__global__ void __launch_bounds__(128)
attn_kernel(const __half* __restrict__ qkv,
            const float* __restrict__ rpb,
            __half* __restrict__ out)
{
    __shared__ __align__(16) __half qs[64 * QK_STR];
    __shared__ __align__(16) __half ks[64 * QK_STR];
    __shared__ __align__(16) __half vT[32 * PV_STR];
    __shared__ __align__(16) __half ps[64 * PV_STR];

    const int bw   = blockIdx.x / NHEADS;
    const int h    = blockIdx.x % NHEADS;
    const int w    = bw % NWIN;
    const int base = bw * NTOK;
    const int tid  = threadIdx.x;
    const int warp = tid >> 5;
    const int lane = tid & 31;
    const int g    = lane >> 2;      // 0..7
    const int t    = lane & 3;       // 0..3
    const int mrow = warp * 16;

    // zero q/k/v smem (pad regions must be 0 to avoid NaNs in MMA)
    {
        uint4 z = make_uint4(0, 0, 0, 0);
        uint4* p0 = (uint4*)qs;
        const int n_q = 64 * QK_STR / 8;             // 320 uint4
        for (int i = tid; i < n_q; i += 128) p0[i] = z;
        uint4* p1 = (uint4*)ks;
        for (int i = tid; i < n_q; i += 128) p1[i] = z;
        uint4* p2 = (uint4*)vT;
        const int n_v = 32 * PV_STR / 8;             // 288 uint4
        for (int i = tid; i < n_v; i += 128) p2[i] = z;
    }
    __syncthreads();

    // load q,k (row-major, K-major) and v transposed [d][j]
    for (int idx = tid; idx < NTOK * 16; idx += 128) {
        int i = idx >> 4, d2 = idx & 15;
        const __half* r = qkv + (size_t)(base + i) * QKV_DIM + h * HDIM + d2 * 2;
        *(__half2*)&qs[i * QK_STR + d2 * 2] = *(const __half2*)(r);
        *(__half2*)&ks[i * QK_STR + d2 * 2] = *(const __half2*)(r + C_DIM);
        __half2 v2 = *(const __half2*)(r + 2 * C_DIM);
        vT[(2 * d2)     * PV_STR + i] = __low2half(v2);
        vT[(2 * d2 + 1) * PV_STR + i] = __high2half(v2);
    }
    __syncthreads();

    // ---- S = Q @ K^T : warp covers rows [mrow, mrow+16), all 64 cols ------
    float c[8][4];
#pragma unroll
    for (int nt = 0; nt < 8; nt++)
#pragma unroll
        for (int e = 0; e < 4; e++) c[nt][e] = 0.f;

#pragma unroll
    for (int kst = 0; kst < 2; kst++) {
        const int kb = kst * 16 + t * 2;
        uint32_t a[4];
        a[0] = *(const uint32_t*)&qs[(mrow + g)     * QK_STR + kb];
        a[1] = *(const uint32_t*)&qs[(mrow + g + 8) * QK_STR + kb];
        a[2] = *(const uint32_t*)&qs[(mrow + g)     * QK_STR + kb + 8];
        a[3] = *(const uint32_t*)&qs[(mrow + g + 8) * QK_STR + kb + 8];
#pragma unroll
        for (int nt = 0; nt < 8; nt++) {
            uint32_t b0 = *(const uint32_t*)&ks[(nt * 8 + g) * QK_STR + kb];
            uint32_t b1 = *(const uint32_t*)&ks[(nt * 8 + g) * QK_STR + kb + 8];
            mma16816(c[nt], a, b0, b1);
        }
    }

    // ---- scale + bias + mask in registers --------------------------------
    const int wh = w >> 3, ww = w & 7;
    const int i0 = mrow + g, i1 = mrow + g + 8;
    const int ri0 = i0 / WSZ, ci0 = i0 % WSZ;
    const int ri1 = i1 / WSZ, ci1 = i1 % WSZ;
    const int rgI0 = ((wh == 7) ? (ri0 < 4 ? 1 : 2) : 0) * 3
                   + ((ww == 7) ? (ci0 < 4 ? 1 : 2) : 0);
    const int rgI1 = ((wh == 7) ? (ri1 < 4 ? 1 : 2) : 0) * 3
                   + ((ww == 7) ? (ci1 < 4 ? 1 : 2) : 0);
    const float scale = 0.17677669529663687f;

#pragma unroll
    for (int nt = 0; nt < 8; nt++) {
#pragma unroll
        for (int jj = 0; jj < 2; jj++) {
            int j = nt * 8 + t * 2 + jj;
            if (j < NTOK) {
                int rj = j / WSZ, cj = j % WSZ;
                int rgJ = ((wh == 7) ? (rj < 4 ? 1 : 2) : 0) * 3
                        + ((ww == 7) ? (cj < 4 ? 1 : 2) : 0);
                float b0 = rpb[((ri0 - rj + 6) * 13 + (ci0 - cj + 6)) * NHEADS + h];
                float b1 = rpb[((ri1 - rj + 6) * 13 + (ci1 - cj + 6)) * NHEADS + h];
                c[nt][jj]     = c[nt][jj]     * scale + b0 + ((rgI0 != rgJ) ? -100.f : 0.f);
                c[nt][jj + 2] = c[nt][jj + 2] * scale + b1 + ((rgI1 != rgJ) ? -100.f : 0.f);
            } else {
                c[nt][jj] = -1e30f;
                c[nt][jj + 2] = -1e30f;
            }
        }
    }

    // ---- softmax in register fragments (row lives in a 4-lane quad) ------
    float m0 = -1e30f, m1 = -1e30f;
#pragma unroll
    for (int nt = 0; nt < 8; nt++) {
        m0 = fmaxf(m0, fmaxf(c[nt][0], c[nt][1]));
        m1 = fmaxf(m1, fmaxf(c[nt][2], c[nt][3]));
    }
    m0 = fmaxf(m0, __shfl_xor_sync(0xffffffffu, m0, 1));
    m0 = fmaxf(m0, __shfl_xor_sync(0xffffffffu, m0, 2));
    m1 = fmaxf(m1, __shfl_xor_sync(0xffffffffu, m1, 1));
    m1 = fmaxf(m1, __shfl_xor_sync(0xffffffffu, m1, 2));

    float s0 = 0.f, s1 = 0.f;
#pragma unroll
    for (int nt = 0; nt < 8; nt++) {
        c[nt][0] = expf(c[nt][0] - m0);
        c[nt][1] = expf(c[nt][1] - m0);
        c[nt][2] = expf(c[nt][2] - m1);
        c[nt][3] = expf(c[nt][3] - m1);
        s0 += c[nt][0] + c[nt][1];
        s1 += c[nt][2] + c[nt][3];
    }
    s0 += __shfl_xor_sync(0xffffffffu, s0, 1);
    s0 += __shfl_xor_sync(0xffffffffu, s0, 2);
    s1 += __shfl_xor_sync(0xffffffffu, s1, 1);
    s1 += __shfl_xor_sync(0xffffffffu, s1, 2);
    const float r0 = 1.f / s0, r1 = 1.f / s1;

#pragma unroll
    for (int nt = 0; nt < 8; nt++) {
        int jcol = nt * 8 + t * 2;
        *(__half2*)&ps[i0 * PV_STR + jcol] = __floats2half2_rn(c[nt][0] * r0, c[nt][1] * r0);
        *(__half2*)&ps[i1 * PV_STR + jcol] = __floats2half2_rn(c[nt][2] * r1, c[nt][3] * r1);
    }
    __syncthreads();

    // ---- O = P @ V  (P [64x64] fp16, V^T [32 dims][64 toks]) -------------
    float o[4][4];
#pragma unroll
    for (int nt = 0; nt < 4; nt++)
#pragma unroll
        for (int e = 0; e < 4; e++) o[nt][e] = 0.f;

#pragma unroll
    for (int kst = 0; kst < 4; kst++) {
        const int kb = kst * 16 + t * 2;
        uint32_t a[4];
        a[0] = *(const uint32_t*)&ps[(mrow + g)     * PV_STR + kb];
        a[1] = *(const uint32_t*)&ps[(mrow + g + 8) * PV_STR + kb];
        a[2] = *(const uint32_t*)&ps[(mrow + g)     * PV_STR + kb + 8];
        a[3] = *(const uint32_t*)&ps[(mrow + g + 8) * PV_STR + kb + 8];
#pragma unroll
        for (int nt = 0; nt < 4; nt++) {
            uint32_t b0 = *(const uint32_t*)&vT[(nt * 8 + g) * PV_STR + kb];
            uint32_t b1 = *(const uint32_t*)&vT[(nt * 8 + g) * PV_STR + kb + 8];
            mma16816(o[nt], a, b0, b1);
        }
    }

    // ---- store O (rows < 49 only) ----------------------------------------
#pragma unroll
    for (int nt = 0; nt < 4; nt++) {
        int d = nt * 8 + t * 2;
        if (i0 < NTOK)
            *(__half2*)(out + (size_t)(base + i0) * C_DIM + h * HDIM + d)
                = __floats2half2_rn(o[nt][0], o[nt][1]);
        if (i1 < NTOK)
            *(__half2*)(out + (size_t)(base + i1) * C_DIM + h * HDIM + d)
                = __floats2half2_rn(o[nt][2], o[nt][3]);
    }
}

// ---------------------------------------------------------------------------
// HMMA GEMM (unchanged from round 4).
// ---------------------------------------------------------------------------
#define BK      32
#define LDS_A   40
#define LDS_B   40

template <int MODE>
__global__ void __launch_bounds__(256)
hmma_gemm(const __half* __restrict__ A, const __half* __restrict__ Bw,
          const float* __restrict__ bias, const float* __restrict__ resid,
          void* __restrict__ Cout, int N, int K)
{
    __shared__ __half As[2][128 * LDS_A];
    __shared__ __half Bs[2][96 * LDS_B];

    const int tid    = threadIdx.x;
    const int warp   = tid >> 5;
    const int lane   = tid & 31;
    const int warp_m = warp & 3;
    const int warp_n = warp >> 2;
    const int bm = blockIdx.y, bn = blockIdx.x;

    const int g = lane >> 2;
    const int t = lane & 3;

    float acc[2][6][4];
#pragma unroll
    for (int mt = 0; mt < 2; mt++)
#pragma unroll
        for (int nt = 0; nt < 6; nt++)
#pragma unroll
            for (int e = 0; e < 4; e++) acc[mt][nt][e] = 0.f;

    const int NC = K >> 5;

    auto load_chunk = [&](int c) {
        const int p  = c & 1;
        const int k0 = c << 5;
#pragma unroll
        for (int i = tid; i < 512; i += 256) {
            int r = i >> 2, s = i & 3;
            cp_async16(smem_u32(&As[p][r * LDS_A + s * 8]),
                       A + (size_t)(bm * 128 + r) * K + k0 + s * 8);
        }
        for (int i = tid; i < 384; i += 256) {
            int r = i >> 2, s = i & 3;
            cp_async16(smem_u32(&Bs[p][r * LDS_B + s * 8]),
                       Bw + (size_t)(bn * 96 + r) * K + k0 + s * 8);
        }
        cp_commit();
    };

    load_chunk(0);

    for (int c = 0; c < NC; c++) {
        if (c + 1 < NC) { load_chunk(c + 1); cp_wait1(); }
        else            { cp_wait0(); }
        __syncthreads();

        const int p = c & 1;
        const __half* a_s = As[p];
        const __half* b_s = Bs[p];

#pragma unroll
        for (int ksub = 0; ksub < 2; ksub++) {
            const int kb = ksub * 16 + t * 2;
            uint32_t afr[2][4];
#pragma unroll
            for (int mt = 0; mt < 2; mt++) {
                int r0 = warp_m * 32 + mt * 16 + g;
                afr[mt][0] = *(const uint32_t*)&a_s[r0 * LDS_A + kb];
                afr[mt][1] = *(const uint32_t*)&a_s[(r0 + 8) * LDS_A + kb];
                afr[mt][2] = *(const uint32_t*)&a_s[r0 * LDS_A + kb + 8];
                afr[mt][3] = *(const uint32_t*)&a_s[(r0 + 8) * LDS_A + kb + 8];
            }
#pragma unroll
            for (int nt = 0; nt < 6; nt++) {
                int n0 = warp_n * 48 + nt * 8 + g;
                uint32_t b0 = *(const uint32_t*)&b_s[n0 * LDS_B + kb];
                uint32_t b1 = *(const uint32_t*)&b_s[n0 * LDS_B + kb + 8];
                mma16816(acc[0][nt], afr[0], b0, b1);
                mma16816(acc[1][nt], afr[1], b0, b1);
            }
        }
        __syncthreads();
    }

#pragma unroll
    for (int mt = 0; mt < 2; mt++) {
        int row = bm * 128 + warp_m * 32 + mt * 16 + g;
        int orow0 = row, orow1 = row + 8;
        if (MODE == 1) {
#pragma unroll
            for (int rr = 0; rr < 2; rr++) {
                int r   = row + rr * 8;
                int b   = r / (NWIN * NTOK);
                int rem = r % (NWIN * NTOK);
                int w   = rem / NTOK;
                int n   = rem % NTOK;
                int gh  = ((w >> 3) * WSZ + n / WSZ + 3) % 56;
                int gw  = ((w & 7)  * WSZ + n % WSZ + 3) % 56;
                int pr  = (b * 56 + gh) * 56 + gw;
                if (rr) orow1 = pr; else orow0 = pr;
            }
        }
#pragma unroll
        for (int nt = 0; nt < 6; nt++) {
            int col = bn * 96 + warp_n * 48 + nt * 8 + t * 2;
            float b0 = bias[col], b1 = bias[col + 1];
            float v0 = acc[mt][nt][0] + b0;
            float v1 = acc[mt][nt][1] + b1;
            float v2 = acc[mt][nt][2] + b0;
            float v3 = acc[mt][nt][3] + b1;
            if (MODE == 0) {
                __half* O = (__half*)Cout;
                *(__half2*)(O + (size_t)row * N + col)       = __floats2half2_rn(v0, v1);
                *(__half2*)(O + (size_t)(row + 8) * N + col) = __floats2half2_rn(v2, v3);
            } else if (MODE == 2) {
                v0 = 0.5f * v0 * (1.f + erff(v0 * 0.70710678118654752f));
                v1 = 0.5f * v1 * (1.f + erff(v1 * 0.70710678118654752f));
                v2 = 0.5f * v2 * (1.f + erff(v2 * 0.70710678118654752f));
                v3 = 0.5f * v3 * (1.f + erff(v3 * 0.70710678118654752f));
                __half* O = (__half*)Cout;
                *(__half2*)(O + (size_t)row * N + col)       = __floats2half2_rn(v0, v1);
                *(__half2*)(O + (size_t)(row + 8) * N + col) = __floats2half2_rn(v2, v3);
            } else {
                float* O = (float*)Cout;
                const float2 rr0 = *(const float2*)(resid + (size_t)orow0 * N + col);
                const float2 rr1 = *(const float2*)(resid + (size_t)orow1 * N + col);
                *(float2*)(O + (size_t)orow0 * N + col) = make_float2(v0 + rr0.x, v1 + rr0.y);
                *(float2*)(O + (size_t)orow1 * N + col) = make_float2(v2 + rr1.x, v3 + rr1.y);
            }
        }
    }
}

// ---------------------------------------------------------------------------
// Launch
// ---------------------------------------------------------------------------
extern "C" void kernel_launch(void* const* d_in, const int* in_sizes, int n_in,
                              void* d_out, int out_size)
{
    const float* x      = (const float*)d_in[0];
    const float* n1g    = (const float*)d_in[1];
    const float* n1b    = (const float*)d_in[2];
    const float* qkv_w  = (const float*)d_in[3];
    const float* qkv_b  = (const float*)d_in[4];
    const float* rpb    = (const float*)d_in[5];
    const float* proj_w = (const float*)d_in[6];
    const float* proj_b = (const float*)d_in[7];
    const float* n2g    = (const float*)d_in[8];
    const float* n2b    = (const float*)d_in[9];
    const float* fc1_w  = (const float*)d_in[10];
    const float* fc1_b  = (const float*)d_in[11];
    const float* fc2_w  = (const float*)d_in[12];
    const float* fc2_b  = (const float*)d_in[13];
    float* out = (float*)d_out;

    __half *xw, *qkvb, *attn, *xn2, *hid, *wqkv, *wproj, *wfc1, *wfc2;
    float  *x1;
    cudaGetSymbolAddress((void**)&xw,    g_xw);
    cudaGetSymbolAddress((void**)&qkvb,  g_qkv);
    cudaGetSymbolAddress((void**)&attn,  g_attn);
    cudaGetSymbolAddress((void**)&x1,    g_x1);
    cudaGetSymbolAddress((void**)&xn2,   g_xn2);
    cudaGetSymbolAddress((void**)&hid,   g_hid);
    cudaGetSymbolAddress((void**)&wqkv,  g_wqkv);
    cudaGetSymbolAddress((void**)&wproj, g_wproj);
    cudaGetSymbolAddress((void**)&wfc1,  g_wfc1);
    cudaGetSymbolAddress((void**)&wfc2,  g_wfc2);

    const int lnBlocks = (T_TOKENS + 7) / 8;

    prep_weights<<<(W_TOTAL + 255) / 256, 256>>>(qkv_w, proj_w, fc1_w, fc2_w);

    ln_kernel<<<lnBlocks, 256>>>(x, n1g, n1b, xw, 1);

    hmma_gemm<0><<<dim3(QKV_DIM / 96, MTILES), 256>>>(
        xw, wqkv, qkv_b, nullptr, qkvb, QKV_DIM, C_DIM);

    attn_kernel<<<(T_TOKENS / NTOK) * NHEADS, 128>>>(qkvb, rpb, attn);

    hmma_gemm<1><<<dim3(C_DIM / 96, MTILES), 256>>>(
        attn, wproj, proj_b, x, x1, C_DIM, C_DIM);

    ln_kernel<<<lnBlocks, 256>>>(x1, n2g, n2b, xn2, 0);

    hmma_gemm<2><<<dim3(HID_DIM / 96, MTILES), 256>>>(
        xn2, wfc1, fc1_b, nullptr, hid, HID_DIM, C_DIM);

    hmma_gemm<3><<<dim3(C_DIM / 96, MTILES), 256>>>(
        hid, wfc2, fc2_b, x1, out, C_DIM, HID_DIM);
}